// round 2
// baseline (speedup 1.0000x reference)
#include <cuda_runtime.h>
#include <math.h>

#define NRES 768
#define CSD  384
#define CZD  128
#define CHD  16
#define NHD  12
#define PQD  4
#define PVD  8
#define INF_ 100000.0f

// ---------------- scratch (device globals; no allocation) ----------------
__device__ float g_se[NRES * CSD];            // se0 after LN
__device__ float g_proj[NRES * 1152];         // [q(192) | kv(384) | qp(144) | kvp(432)]
__device__ float g_qhat[NRES * 336];          // per n: 12 heads x 28
__device__ float g_khat[NRES * 336];
__device__ float g_kc[NRES * NHD];            // -0.5*hw*sum|k_pts|^2
__device__ float g_vall[NRES * NHD * 40];     // per (n,h): v(16) + v_pts(24)
__device__ float g_optp[NRES * NHD * 24];     // o_pt before inverse frame
__device__ float g_cat[NRES * 2112];
__device__ float g_logits[NHD * NRES * NRES]; // layout [i][h][j]

// ---------------- generic tiled GEMM: C = A(MxK) @ W(NxK)^T + bias ----------------
// BM=BN=64, BK=16, 256 threads, 4x4 microtile. K % 16 == 0, M % 64 == 0.
__global__ void k_gemm(const float* __restrict__ A, const float* __restrict__ W,
                       const float* __restrict__ bias, float* __restrict__ C,
                       int M, int Nn, int K, int ldc, int coff) {
    __shared__ __align__(16) float As[16][65];
    __shared__ __align__(16) float Ws[16][65];
    int t  = threadIdx.x;
    int tx = t & 15, ty = t >> 4;
    int m0 = blockIdx.y * 64, n0 = blockIdx.x * 64;
    float acc[4][4] = {};
    for (int kt = 0; kt < K; kt += 16) {
        #pragma unroll
        for (int l = 0; l < 4; l++) {
            int idx = t + l * 256;
            int mm = idx >> 4, kk = idx & 15;
            As[kk][mm] = A[(size_t)(m0 + mm) * K + kt + kk];
            Ws[kk][mm] = (n0 + mm < Nn) ? W[(size_t)(n0 + mm) * K + kt + kk] : 0.f;
        }
        __syncthreads();
        #pragma unroll
        for (int k = 0; k < 16; k++) {
            float av[4], wv[4];
            #pragma unroll
            for (int a = 0; a < 4; a++) av[a] = As[k][ty + 16 * a];
            #pragma unroll
            for (int b = 0; b < 4; b++) wv[b] = Ws[k][tx + 16 * b];
            #pragma unroll
            for (int a = 0; a < 4; a++)
                #pragma unroll
                for (int b = 0; b < 4; b++) acc[a][b] += av[a] * wv[b];
        }
        __syncthreads();
    }
    #pragma unroll
    for (int a = 0; a < 4; a++) {
        int m = m0 + ty + 16 * a;
        #pragma unroll
        for (int b = 0; b < 4; b++) {
            int n = n0 + tx + 16 * b;
            if (n < Nn) C[(size_t)m * ldc + coff + n] = acc[a][b] + bias[n];
        }
    }
}

// ---------------- LayerNorm in place on g_se (768 rows x 384) ----------------
__global__ void k_ln(const float* __restrict__ gamma, const float* __restrict__ beta) {
    int n = blockIdx.x, t = threadIdx.x;
    float* row = g_se + (size_t)n * CSD;
    float x0 = row[t], x1 = row[t + 128], x2 = row[t + 256];
    float s1 = x0 + x1 + x2;
    float s2 = x0 * x0 + x1 * x1 + x2 * x2;
    __shared__ float r1[4], r2[4];
    #pragma unroll
    for (int o = 16; o; o >>= 1) {
        s1 += __shfl_xor_sync(0xffffffffu, s1, o);
        s2 += __shfl_xor_sync(0xffffffffu, s2, o);
    }
    if ((t & 31) == 0) { r1[t >> 5] = s1; r2[t >> 5] = s2; }
    __syncthreads();
    float ts1 = r1[0] + r1[1] + r1[2] + r1[3];
    float ts2 = r2[0] + r2[1] + r2[2] + r2[3];
    float mu  = ts1 * (1.f / 384.f);
    float var = ts2 * (1.f / 384.f) - mu * mu;
    float inv = rsqrtf(var + 1e-5f);
    row[t]       = (x0 - mu) * inv * gamma[t]       + beta[t];
    row[t + 128] = (x1 - mu) * inv * gamma[t + 128] + beta[t + 128];
    row[t + 256] = (x2 - mu) * inv * gamma[t + 256] + beta[t + 256];
}

// ---------------- assemble qhat/khat/kconst/v/v_pts (frame 0 only) ----------------
__global__ void k_assemble(const float* __restrict__ r_rot, const float* __restrict__ r_trans,
                           const float* __restrict__ head_w) {
    int gw   = blockIdx.x * 8 + (threadIdx.x >> 5);
    int lane = threadIdx.x & 31;
    if (gw >= NRES || lane >= NHD) return;
    int n = gw, h = lane;
    float rot[9], t0[3];
    #pragma unroll
    for (int i = 0; i < 9; i++) rot[i] = r_rot[n * 45 + i];       // frame 0
    #pragma unroll
    for (int i = 0; i < 3; i++) t0[i] = r_trans[n * 15 + i];
    float hw = log1pf(expf(head_w[h])) * rsqrtf(54.0f);           // softplus * sqrt(1/(3*18))
    const float c1 = rsqrtf(48.0f);                               // 1/sqrt(3*CH)
    const float* P = g_proj + (size_t)n * 1152;
    float* qh = g_qhat + (size_t)n * 336 + h * 28;
    float* kh = g_khat + (size_t)n * 336 + h * 28;
    float* va = g_vall + ((size_t)n * NHD + h) * 40;
    #pragma unroll
    for (int c = 0; c < 16; c++) {
        qh[c] = c1 * P[h * 16 + c];
        kh[c] = P[192 + h * 32 + c];
        va[c] = P[192 + h * 32 + 16 + c];
    }
    // q points (rotate + translate, scale by hw)
    #pragma unroll
    for (int pp = 0; pp < 4; pp++) {
        float l0 = P[576 +   0 + h * 4 + pp];
        float l1 = P[576 +  48 + h * 4 + pp];
        float l2 = P[576 +  96 + h * 4 + pp];
        #pragma unroll
        for (int i = 0; i < 3; i++) {
            float o = rot[i * 3] * l0 + rot[i * 3 + 1] * l1 + rot[i * 3 + 2] * l2 + t0[i];
            qh[16 + pp * 3 + i] = hw * o;
        }
    }
    // k points + kconst
    float kc = 0.f;
    #pragma unroll
    for (int pp = 0; pp < 4; pp++) {
        float l0 = P[720 +   0 + h * 12 + pp];
        float l1 = P[720 + 144 + h * 12 + pp];
        float l2 = P[720 + 288 + h * 12 + pp];
        #pragma unroll
        for (int i = 0; i < 3; i++) {
            float o = rot[i * 3] * l0 + rot[i * 3 + 1] * l1 + rot[i * 3 + 2] * l2 + t0[i];
            kh[16 + pp * 3 + i] = o;
            kc += o * o;
        }
    }
    g_kc[n * NHD + h] = -0.5f * hw * kc;
    // v points
    #pragma unroll
    for (int pv = 0; pv < 8; pv++) {
        int pp = 4 + pv;
        float l0 = P[720 +   0 + h * 12 + pp];
        float l1 = P[720 + 144 + h * 12 + pp];
        float l2 = P[720 + 288 + h * 12 + pp];
        #pragma unroll
        for (int i = 0; i < 3; i++) {
            float o = rot[i * 3] * l0 + rot[i * 3 + 1] * l1 + rot[i * 3 + 2] * l2 + t0[i];
            va[16 + pv * 3 + i] = o;
        }
    }
}

// ---------------- logits: qk(28-dot) + z-bias + kconst + mask ----------------
__global__ void k_logits(const float* __restrict__ z, const float* __restrict__ wb,
                         const float* __restrict__ bb, const float* __restrict__ mask) {
    __shared__ __align__(16) float qh_s[336];
    __shared__ __align__(16) float wb_s[NHD * 128];
    __shared__ float bb_s[NHD];
    __shared__ float ulri_s;
    int i = blockIdx.y;
    int j = blockIdx.x * 256 + threadIdx.x;
    int t = threadIdx.x;
    const float c2 = 0.57735026918962576f;  // sqrt(1/3)
    for (int idx = t; idx < 336; idx += 256) qh_s[idx] = g_qhat[(size_t)i * 336 + idx];
    for (int idx = t; idx < NHD * 128; idx += 256) wb_s[idx] = c2 * wb[idx];
    if (t < NHD) bb_s[t] = c2 * bb[t];
    if (t == 0) ulri_s = mask[i * 5];
    __syncthreads();
    float ulrj  = mask[j * 5];
    float mterm = INF_ * (ulri_s * ulrj - 1.0f);
    float acc[NHD];
    #pragma unroll
    for (int h = 0; h < NHD; h++) acc[h] = bb_s[h] + g_kc[j * NHD + h] + mterm;
    const float4* z4 = reinterpret_cast<const float4*>(z + ((size_t)i * NRES + j) * CZD);
    #pragma unroll 4
    for (int cc = 0; cc < 32; cc++) {
        float4 zz = z4[cc];
        #pragma unroll
        for (int h = 0; h < NHD; h++) {
            float4 wv = *reinterpret_cast<const float4*>(&wb_s[h * 128 + cc * 4]);
            acc[h] += zz.x * wv.x + zz.y * wv.y + zz.z * wv.z + zz.w * wv.w;
        }
    }
    const float* khj = g_khat + (size_t)j * 336;
    #pragma unroll
    for (int h = 0; h < NHD; h++) {
        float s = 0.f;
        #pragma unroll
        for (int d = 0; d < 7; d++) {
            float4 k4 = *reinterpret_cast<const float4*>(khj + h * 28 + d * 4);
            float4 q4 = *reinterpret_cast<const float4*>(&qh_s[h * 28 + d * 4]);
            s += k4.x * q4.x + k4.y * q4.y + k4.z * q4.z + k4.w * q4.w;
        }
        g_logits[((size_t)i * NHD + h) * NRES + j] = acc[h] + s;
    }
}

// ---------------- softmax (in place) + o_pair ----------------
__global__ void k_attn_out(const float* __restrict__ z) {
    extern __shared__ float sm[];
    float* a_t  = sm;                 // 768*12 floats (a transposed [j][h])
    float* part = sm + NRES * NHD;    // 2*12*128 floats
    int i = blockIdx.x;
    int t = threadIdx.x;
    int warp = t >> 5, lane = t & 31;
    for (int h = warp; h < NHD; h += 8) {
        float* row = g_logits + ((size_t)i * NHD + h) * NRES;
        float x[24];
        float mx = -1e30f;
        #pragma unroll
        for (int kk = 0; kk < 24; kk++) { x[kk] = row[lane + kk * 32]; mx = fmaxf(mx, x[kk]); }
        #pragma unroll
        for (int o = 16; o; o >>= 1) mx = fmaxf(mx, __shfl_xor_sync(0xffffffffu, mx, o));
        float s = 0.f;
        #pragma unroll
        for (int kk = 0; kk < 24; kk++) { x[kk] = __expf(x[kk] - mx); s += x[kk]; }
        #pragma unroll
        for (int o = 16; o; o >>= 1) s += __shfl_xor_sync(0xffffffffu, s, o);
        float r = 1.0f / s;
        #pragma unroll
        for (int kk = 0; kk < 24; kk++) {
            float a = x[kk] * r;
            int jj = lane + kk * 32;
            row[jj] = a;
            a_t[jj * NHD + h] = a;
        }
    }
    __syncthreads();
    int c = t & 127, half = t >> 7;
    const float* zp = z + ((size_t)i * NRES + half * 384) * CZD + c;
    float acc[NHD] = {};
    for (int j = 0; j < 384; j++) {
        float zv = zp[(size_t)j * CZD];
        const float* aa = a_t + (half * 384 + j) * NHD;
        float4 a0 = *reinterpret_cast<const float4*>(aa);
        float4 a1 = *reinterpret_cast<const float4*>(aa + 4);
        float4 a2 = *reinterpret_cast<const float4*>(aa + 8);
        acc[0] += a0.x * zv; acc[1]  += a0.y * zv; acc[2]  += a0.z * zv; acc[3]  += a0.w * zv;
        acc[4] += a1.x * zv; acc[5]  += a1.y * zv; acc[6]  += a1.z * zv; acc[7]  += a1.w * zv;
        acc[8] += a2.x * zv; acc[9]  += a2.y * zv; acc[10] += a2.z * zv; acc[11] += a2.w * zv;
    }
    #pragma unroll
    for (int h = 0; h < NHD; h++) part[(half * NHD + h) * 128 + c] = acc[h];
    __syncthreads();
    for (int idx = t; idx < NHD * 128; idx += 256)
        g_cat[(size_t)i * 2112 + 576 + idx] = part[idx] + part[NHD * 128 + idx];
}

// ---------------- o = a@v, o_pt_pre = a@v_pts (per head, tiled) ----------------
__global__ void k_ov() {
    __shared__ float a_s[64][65];
    __shared__ float v_s[64][40];
    int i0 = blockIdx.x * 64;
    int h  = blockIdx.y;
    int t  = threadIdx.x;
    int r = t & 63, cg = t >> 6;
    float acc[10] = {};
    for (int jt = 0; jt < NRES; jt += 64) {
        #pragma unroll
        for (int l = 0; l < 16; l++) {
            int idx = t + l * 256;
            a_s[idx >> 6][idx & 63] =
                g_logits[((size_t)(i0 + (idx >> 6)) * NHD + h) * NRES + jt + (idx & 63)];
        }
        #pragma unroll
        for (int l = 0; l < 10; l++) {
            int idx = t + l * 256;
            v_s[idx / 40][idx % 40] =
                g_vall[((size_t)(jt + idx / 40) * NHD + h) * 40 + idx % 40];
        }
        __syncthreads();
        #pragma unroll 8
        for (int k = 0; k < 64; k++) {
            float av = a_s[r][k];
            #pragma unroll
            for (int q = 0; q < 10; q++) acc[q] += av * v_s[k][cg * 10 + q];
        }
        __syncthreads();
    }
    #pragma unroll
    for (int q = 0; q < 10; q++) {
        int c = cg * 10 + q;
        if (c < 16) g_cat[(size_t)(i0 + r) * 2112 + h * 16 + c] = acc[q];
        else        g_optp[((size_t)(i0 + r) * NHD + h) * 24 + (c - 16)] = acc[q];
    }
}

// ---------------- inverse frame transform + norms into g_cat ----------------
__global__ void k_finalize(const float* __restrict__ r_rot, const float* __restrict__ r_trans) {
    int id = blockIdx.x * 256 + threadIdx.x;
    if (id >= NRES * 96) return;
    int n = id / 96, rr = id % 96;
    int h = rr >> 3, pv = rr & 7;
    const float* p = g_optp + ((size_t)n * NHD + h) * 24 + pv * 3;
    float d0 = p[0] - r_trans[n * 15 + 0];
    float d1 = p[1] - r_trans[n * 15 + 1];
    float d2 = p[2] - r_trans[n * 15 + 2];
    const float* R = r_rot + n * 45;
    float o0 = R[0] * d0 + R[3] * d1 + R[6] * d2;   // out[k] = sum_i R[i][k]*d[i]
    float o1 = R[1] * d0 + R[4] * d1 + R[7] * d2;
    float o2 = R[2] * d0 + R[5] * d1 + R[8] * d2;
    float nm = sqrtf(o0 * o0 + o1 * o1 + o2 * o2 + 1e-8f);
    float* cb = g_cat + (size_t)n * 2112 + 192;
    cb[rr] = o0; cb[96 + rr] = o1; cb[192 + rr] = o2; cb[288 + rr] = nm;
}

// ---------------- launch ----------------
extern "C" void kernel_launch(void* const* d_in, const int* in_sizes, int n_in,
                              void* d_out, int out_size) {
    const float* s       = (const float*)d_in[0];
    const float* z       = (const float*)d_in[1];
    const float* r_rot   = (const float*)d_in[2];
    const float* r_trans = (const float*)d_in[3];
    const float* mask    = (const float*)d_in[4];
    const float* wq      = (const float*)d_in[5];
    const float* bq      = (const float*)d_in[6];
    const float* wkv     = (const float*)d_in[7];
    const float* bkv     = (const float*)d_in[8];
    const float* wqp     = (const float*)d_in[9];
    const float* bqp     = (const float*)d_in[10];
    const float* wkvp    = (const float*)d_in[11];
    const float* bkvp    = (const float*)d_in[12];
    const float* wb      = (const float*)d_in[13];
    const float* bb      = (const float*)d_in[14];
    const float* head_w  = (const float*)d_in[15];
    const float* wout    = (const float*)d_in[16];
    const float* bout    = (const float*)d_in[17];
    const float* wexp    = (const float*)d_in[18];
    const float* bexp    = (const float*)d_in[19];
    const float* ln_g    = (const float*)d_in[20];
    const float* ln_b    = (const float*)d_in[21];
    // d_in[22] = ww, d_in[23] = bw : softmax over singleton axis -> weight == 1, unused.
    float* out = (float*)d_out;

    float *p_se = nullptr, *p_proj = nullptr, *p_cat = nullptr;
    cudaGetSymbolAddress((void**)&p_se,   g_se);
    cudaGetSymbolAddress((void**)&p_proj, g_proj);
    cudaGetSymbolAddress((void**)&p_cat,  g_cat);

    // se0 = LN(s @ wexp[0:384]^T + bexp[0:384])
    k_gemm<<<dim3(6, 12), 256>>>(s, wexp, bexp, p_se, 768, 384, 384, 384, 0);
    k_ln<<<768, 128>>>(ln_g, ln_b);

    // projections into g_proj columns
    k_gemm<<<dim3(3, 12), 256>>>(p_se, wq,   bq,   p_proj, 768, 192, 384, 1152, 0);
    k_gemm<<<dim3(6, 12), 256>>>(p_se, wkv,  bkv,  p_proj, 768, 384, 384, 1152, 192);
    k_gemm<<<dim3(3, 12), 256>>>(p_se, wqp,  bqp,  p_proj, 768, 144, 384, 1152, 576);
    k_gemm<<<dim3(7, 12), 256>>>(p_se, wkvp, bkvp, p_proj, 768, 432, 384, 1152, 720);

    k_assemble<<<96, 256>>>(r_rot, r_trans, head_w);
    k_logits<<<dim3(3, 768), 256>>>(z, wb, bb, mask);
    k_attn_out<<<768, 256, (NRES * NHD + 2 * NHD * 128) * sizeof(float)>>>(z);
    k_ov<<<dim3(12, 12), 256>>>();
    k_finalize<<<288, 256>>>(r_rot, r_trans);

    // out = cat @ wout^T + bout
    k_gemm<<<dim3(6, 12), 256>>>(p_cat, wout, bout, out, 768, 384, 2112, 384, 0);
}

// round 3
// speedup vs baseline: 1.3963x; 1.3963x over previous
#include <cuda_runtime.h>
#include <math.h>

#define NRES 768
#define CSD  384
#define CZD  128
#define CHD  16
#define NHD  12
#define PQD  4
#define PVD  8
#define INF_ 100000.0f

// ---------------- scratch (device globals; no allocation) ----------------
__device__ float g_se[NRES * CSD];            // se0 after LN
__device__ float g_proj[NRES * 1152];         // [q(192) | kv(384) | qp(144) | kvp(432)]
__device__ float g_qhat[NRES * 336];          // per n: 12 heads x 28
__device__ float g_khat[NRES * 336];
__device__ float g_kc[NRES * NHD];            // -0.5*hw*sum|k_pts|^2
__device__ float g_vall[NRES * NHD * 40];     // per (n,h): v(16) + v_pts(24)
__device__ float g_optp[NRES * NHD * 24];     // o_pt before inverse frame
__device__ float g_cat[NRES * 2112];
__device__ float g_part[2][NRES * CSD];       // split-K partials of final GEMM
__device__ float g_logits[NHD * NRES * NRES]; // layout [i][h][j]

// =====================================================================
// High-throughput fp32 GEMM: C = A(M x K) @ W(N x K)^T [+ bias]
// 64x64 tile, BK=16, 256 threads, 4x4 microtile via LDS.128,
// double-buffered smem with register prefetch.
// grid = (N/64, M/64, splits). ld(A)=ld(W)=ld. partStride selects output
// buffer per blockIdx.z (split-K).
// =====================================================================
__global__ __launch_bounds__(256) void k_gemm64(
    const float* __restrict__ A, const float* __restrict__ W,
    const float* __restrict__ bias, float* __restrict__ C,
    int ld, int ldc, int nkt, int add_bias, int partStride)
{
    __shared__ __align__(16) float As[2][16][68];
    __shared__ __align__(16) float Ws[2][16][68];
    int t  = threadIdx.x;
    int m0 = blockIdx.y * 64, n0 = blockIdx.x * 64;
    int kt0 = blockIdx.z * nkt;
    C += (size_t)blockIdx.z * partStride;

    int lr = t >> 2;            // 0..63 tile row
    int lk = (t & 3) * 4;       // k sub-offset
    const float* arow = A + (size_t)(m0 + lr) * ld + kt0 * 16 + lk;
    const float* wrow = W + (size_t)(n0 + lr) * ld + kt0 * 16 + lk;
    int tx = t & 15, ty = t >> 4;

    float acc[4][4] = {};
    float4 ra = *(const float4*)arow;
    float4 rw = *(const float4*)wrow;
    int buf = 0;
    As[0][lk + 0][lr] = ra.x; As[0][lk + 1][lr] = ra.y;
    As[0][lk + 2][lr] = ra.z; As[0][lk + 3][lr] = ra.w;
    Ws[0][lk + 0][lr] = rw.x; Ws[0][lk + 1][lr] = rw.y;
    Ws[0][lk + 2][lr] = rw.z; Ws[0][lk + 3][lr] = rw.w;

    for (int kt = 0; kt < nkt - 1; kt++) {
        __syncthreads();
        ra = *(const float4*)(arow + (kt + 1) * 16);
        rw = *(const float4*)(wrow + (kt + 1) * 16);
        const float* Ab = &As[buf][0][0];
        const float* Wb = &Ws[buf][0][0];
        #pragma unroll
        for (int k = 0; k < 16; k++) {
            float4 av = *(const float4*)(Ab + k * 68 + ty * 4);
            float4 wv = *(const float4*)(Wb + k * 68 + tx * 4);
            acc[0][0] += av.x * wv.x; acc[0][1] += av.x * wv.y; acc[0][2] += av.x * wv.z; acc[0][3] += av.x * wv.w;
            acc[1][0] += av.y * wv.x; acc[1][1] += av.y * wv.y; acc[1][2] += av.y * wv.z; acc[1][3] += av.y * wv.w;
            acc[2][0] += av.z * wv.x; acc[2][1] += av.z * wv.y; acc[2][2] += av.z * wv.z; acc[2][3] += av.z * wv.w;
            acc[3][0] += av.w * wv.x; acc[3][1] += av.w * wv.y; acc[3][2] += av.w * wv.z; acc[3][3] += av.w * wv.w;
        }
        int nb = buf ^ 1;
        As[nb][lk + 0][lr] = ra.x; As[nb][lk + 1][lr] = ra.y;
        As[nb][lk + 2][lr] = ra.z; As[nb][lk + 3][lr] = ra.w;
        Ws[nb][lk + 0][lr] = rw.x; Ws[nb][lk + 1][lr] = rw.y;
        Ws[nb][lk + 2][lr] = rw.z; Ws[nb][lk + 3][lr] = rw.w;
        buf = nb;
    }
    __syncthreads();
    {
        const float* Ab = &As[buf][0][0];
        const float* Wb = &Ws[buf][0][0];
        #pragma unroll
        for (int k = 0; k < 16; k++) {
            float4 av = *(const float4*)(Ab + k * 68 + ty * 4);
            float4 wv = *(const float4*)(Wb + k * 68 + tx * 4);
            acc[0][0] += av.x * wv.x; acc[0][1] += av.x * wv.y; acc[0][2] += av.x * wv.z; acc[0][3] += av.x * wv.w;
            acc[1][0] += av.y * wv.x; acc[1][1] += av.y * wv.y; acc[1][2] += av.y * wv.z; acc[1][3] += av.y * wv.w;
            acc[2][0] += av.z * wv.x; acc[2][1] += av.z * wv.y; acc[2][2] += av.z * wv.z; acc[2][3] += av.z * wv.w;
            acc[3][0] += av.w * wv.x; acc[3][1] += av.w * wv.y; acc[3][2] += av.w * wv.z; acc[3][3] += av.w * wv.w;
        }
    }
    float4 bv = make_float4(0.f, 0.f, 0.f, 0.f);
    if (add_bias) bv = *(const float4*)(bias + n0 + tx * 4);
    #pragma unroll
    for (int a = 0; a < 4; a++) {
        float4 r = make_float4(acc[a][0] + bv.x, acc[a][1] + bv.y,
                               acc[a][2] + bv.z, acc[a][3] + bv.w);
        *(float4*)(C + (size_t)(m0 + ty * 4 + a) * ldc + n0 + tx * 4) = r;
    }
}

// Fused projection GEMM: g_proj[768 x 1152] = g_se @ [wq|wkv|wqp|wkvp]^T + bias
__device__ __forceinline__ float proj_bias(int n, const float* bq, const float* bkv,
                                           const float* bqp, const float* bkvp) {
    if (n < 192) return bq[n];
    if (n < 576) return bkv[n - 192];
    if (n < 720) return bqp[n - 576];
    return bkvp[n - 720];
}

__global__ __launch_bounds__(256) void k_gemm_proj(
    const float* __restrict__ wq,  const float* __restrict__ bq,
    const float* __restrict__ wkv, const float* __restrict__ bkv,
    const float* __restrict__ wqp, const float* __restrict__ bqp,
    const float* __restrict__ wkvp,const float* __restrict__ bkvp)
{
    __shared__ __align__(16) float As[2][16][68];
    __shared__ __align__(16) float Ws[2][16][68];
    int t  = threadIdx.x;
    int m0 = blockIdx.y * 64, n0 = blockIdx.x * 64;
    int lr = t >> 2;
    int lk = (t & 3) * 4;
    const float* arow = g_se + (size_t)(m0 + lr) * 384 + lk;
    int n = n0 + lr;
    const float* wbase; int nl;
    if      (n < 192) { wbase = wq;   nl = n; }
    else if (n < 576) { wbase = wkv;  nl = n - 192; }
    else if (n < 720) { wbase = wqp;  nl = n - 576; }
    else              { wbase = wkvp; nl = n - 720; }
    const float* wrow = wbase + (size_t)nl * 384 + lk;
    int tx = t & 15, ty = t >> 4;

    float acc[4][4] = {};
    float4 ra = *(const float4*)arow;
    float4 rw = *(const float4*)wrow;
    int buf = 0;
    As[0][lk + 0][lr] = ra.x; As[0][lk + 1][lr] = ra.y;
    As[0][lk + 2][lr] = ra.z; As[0][lk + 3][lr] = ra.w;
    Ws[0][lk + 0][lr] = rw.x; Ws[0][lk + 1][lr] = rw.y;
    Ws[0][lk + 2][lr] = rw.z; Ws[0][lk + 3][lr] = rw.w;

    const int nkt = 24;
    for (int kt = 0; kt < nkt - 1; kt++) {
        __syncthreads();
        ra = *(const float4*)(arow + (kt + 1) * 16);
        rw = *(const float4*)(wrow + (kt + 1) * 16);
        const float* Ab = &As[buf][0][0];
        const float* Wb = &Ws[buf][0][0];
        #pragma unroll
        for (int k = 0; k < 16; k++) {
            float4 av = *(const float4*)(Ab + k * 68 + ty * 4);
            float4 wv = *(const float4*)(Wb + k * 68 + tx * 4);
            acc[0][0] += av.x * wv.x; acc[0][1] += av.x * wv.y; acc[0][2] += av.x * wv.z; acc[0][3] += av.x * wv.w;
            acc[1][0] += av.y * wv.x; acc[1][1] += av.y * wv.y; acc[1][2] += av.y * wv.z; acc[1][3] += av.y * wv.w;
            acc[2][0] += av.z * wv.x; acc[2][1] += av.z * wv.y; acc[2][2] += av.z * wv.z; acc[2][3] += av.z * wv.w;
            acc[3][0] += av.w * wv.x; acc[3][1] += av.w * wv.y; acc[3][2] += av.w * wv.z; acc[3][3] += av.w * wv.w;
        }
        int nb = buf ^ 1;
        As[nb][lk + 0][lr] = ra.x; As[nb][lk + 1][lr] = ra.y;
        As[nb][lk + 2][lr] = ra.z; As[nb][lk + 3][lr] = ra.w;
        Ws[nb][lk + 0][lr] = rw.x; Ws[nb][lk + 1][lr] = rw.y;
        Ws[nb][lk + 2][lr] = rw.z; Ws[nb][lk + 3][lr] = rw.w;
        buf = nb;
    }
    __syncthreads();
    {
        const float* Ab = &As[buf][0][0];
        const float* Wb = &Ws[buf][0][0];
        #pragma unroll
        for (int k = 0; k < 16; k++) {
            float4 av = *(const float4*)(Ab + k * 68 + ty * 4);
            float4 wv = *(const float4*)(Wb + k * 68 + tx * 4);
            acc[0][0] += av.x * wv.x; acc[0][1] += av.x * wv.y; acc[0][2] += av.x * wv.z; acc[0][3] += av.x * wv.w;
            acc[1][0] += av.y * wv.x; acc[1][1] += av.y * wv.y; acc[1][2] += av.y * wv.z; acc[1][3] += av.y * wv.w;
            acc[2][0] += av.z * wv.x; acc[2][1] += av.z * wv.y; acc[2][2] += av.z * wv.z; acc[2][3] += av.z * wv.w;
            acc[3][0] += av.w * wv.x; acc[3][1] += av.w * wv.y; acc[3][2] += av.w * wv.z; acc[3][3] += av.w * wv.w;
        }
    }
    int nc = n0 + tx * 4;
    float4 bv = make_float4(proj_bias(nc + 0, bq, bkv, bqp, bkvp),
                            proj_bias(nc + 1, bq, bkv, bqp, bkvp),
                            proj_bias(nc + 2, bq, bkv, bqp, bkvp),
                            proj_bias(nc + 3, bq, bkv, bqp, bkvp));
    #pragma unroll
    for (int a = 0; a < 4; a++) {
        float4 r = make_float4(acc[a][0] + bv.x, acc[a][1] + bv.y,
                               acc[a][2] + bv.z, acc[a][3] + bv.w);
        *(float4*)(g_proj + (size_t)(m0 + ty * 4 + a) * 1152 + nc) = r;
    }
}

// combine split-K partials + bias -> out
__global__ void k_combine(const float* __restrict__ bout, float* __restrict__ out) {
    int i = blockIdx.x * 256 + threadIdx.x;   // 768*384 total
    out[i] = g_part[0][i] + g_part[1][i] + bout[i % 384];
}

// ---------------- LayerNorm in place on g_se (768 rows x 384) ----------------
__global__ void k_ln(const float* __restrict__ gamma, const float* __restrict__ beta) {
    int n = blockIdx.x, t = threadIdx.x;
    float* row = g_se + (size_t)n * CSD;
    float x0 = row[t], x1 = row[t + 128], x2 = row[t + 256];
    float s1 = x0 + x1 + x2;
    float s2 = x0 * x0 + x1 * x1 + x2 * x2;
    __shared__ float r1[4], r2[4];
    #pragma unroll
    for (int o = 16; o; o >>= 1) {
        s1 += __shfl_xor_sync(0xffffffffu, s1, o);
        s2 += __shfl_xor_sync(0xffffffffu, s2, o);
    }
    if ((t & 31) == 0) { r1[t >> 5] = s1; r2[t >> 5] = s2; }
    __syncthreads();
    float ts1 = r1[0] + r1[1] + r1[2] + r1[3];
    float ts2 = r2[0] + r2[1] + r2[2] + r2[3];
    float mu  = ts1 * (1.f / 384.f);
    float var = ts2 * (1.f / 384.f) - mu * mu;
    float inv = rsqrtf(var + 1e-5f);
    row[t]       = (x0 - mu) * inv * gamma[t]       + beta[t];
    row[t + 128] = (x1 - mu) * inv * gamma[t + 128] + beta[t + 128];
    row[t + 256] = (x2 - mu) * inv * gamma[t + 256] + beta[t + 256];
}

// ---------------- assemble qhat/khat/kconst/v/v_pts (frame 0 only) ----------------
__global__ void k_assemble(const float* __restrict__ r_rot, const float* __restrict__ r_trans,
                           const float* __restrict__ head_w) {
    int gw   = blockIdx.x * 8 + (threadIdx.x >> 5);
    int lane = threadIdx.x & 31;
    if (gw >= NRES || lane >= NHD) return;
    int n = gw, h = lane;
    float rot[9], t0[3];
    #pragma unroll
    for (int i = 0; i < 9; i++) rot[i] = r_rot[n * 45 + i];       // frame 0
    #pragma unroll
    for (int i = 0; i < 3; i++) t0[i] = r_trans[n * 15 + i];
    float hw = log1pf(expf(head_w[h])) * rsqrtf(54.0f);           // softplus * sqrt(1/(3*18))
    const float c1 = rsqrtf(48.0f);                               // 1/sqrt(3*CH)
    const float* P = g_proj + (size_t)n * 1152;
    float* qh = g_qhat + (size_t)n * 336 + h * 28;
    float* kh = g_khat + (size_t)n * 336 + h * 28;
    float* va = g_vall + ((size_t)n * NHD + h) * 40;
    #pragma unroll
    for (int c = 0; c < 16; c++) {
        qh[c] = c1 * P[h * 16 + c];
        kh[c] = P[192 + h * 32 + c];
        va[c] = P[192 + h * 32 + 16 + c];
    }
    #pragma unroll
    for (int pp = 0; pp < 4; pp++) {
        float l0 = P[576 +   0 + h * 4 + pp];
        float l1 = P[576 +  48 + h * 4 + pp];
        float l2 = P[576 +  96 + h * 4 + pp];
        #pragma unroll
        for (int i = 0; i < 3; i++) {
            float o = rot[i * 3] * l0 + rot[i * 3 + 1] * l1 + rot[i * 3 + 2] * l2 + t0[i];
            qh[16 + pp * 3 + i] = hw * o;
        }
    }
    float kc = 0.f;
    #pragma unroll
    for (int pp = 0; pp < 4; pp++) {
        float l0 = P[720 +   0 + h * 12 + pp];
        float l1 = P[720 + 144 + h * 12 + pp];
        float l2 = P[720 + 288 + h * 12 + pp];
        #pragma unroll
        for (int i = 0; i < 3; i++) {
            float o = rot[i * 3] * l0 + rot[i * 3 + 1] * l1 + rot[i * 3 + 2] * l2 + t0[i];
            kh[16 + pp * 3 + i] = o;
            kc += o * o;
        }
    }
    g_kc[n * NHD + h] = -0.5f * hw * kc;
    #pragma unroll
    for (int pv = 0; pv < 8; pv++) {
        int pp = 4 + pv;
        float l0 = P[720 +   0 + h * 12 + pp];
        float l1 = P[720 + 144 + h * 12 + pp];
        float l2 = P[720 + 288 + h * 12 + pp];
        #pragma unroll
        for (int i = 0; i < 3; i++) {
            float o = rot[i * 3] * l0 + rot[i * 3 + 1] * l1 + rot[i * 3 + 2] * l2 + t0[i];
            va[16 + pv * 3 + i] = o;
        }
    }
}

// ---------------- logits: qk(28-dot) + z-bias + kconst + mask ----------------
__global__ void k_logits(const float* __restrict__ z, const float* __restrict__ wb,
                         const float* __restrict__ bb, const float* __restrict__ mask) {
    __shared__ __align__(16) float qh_s[336];
    __shared__ __align__(16) float wb_s[NHD * 128];
    __shared__ float bb_s[NHD];
    __shared__ float ulri_s;
    int i = blockIdx.y;
    int j = blockIdx.x * 256 + threadIdx.x;
    int t = threadIdx.x;
    const float c2 = 0.57735026918962576f;  // sqrt(1/3)
    for (int idx = t; idx < 336; idx += 256) qh_s[idx] = g_qhat[(size_t)i * 336 + idx];
    for (int idx = t; idx < NHD * 128; idx += 256) wb_s[idx] = c2 * wb[idx];
    if (t < NHD) bb_s[t] = c2 * bb[t];
    if (t == 0) ulri_s = mask[i * 5];
    __syncthreads();
    float ulrj  = mask[j * 5];
    float mterm = INF_ * (ulri_s * ulrj - 1.0f);
    float acc[NHD];
    #pragma unroll
    for (int h = 0; h < NHD; h++) acc[h] = bb_s[h] + g_kc[j * NHD + h] + mterm;
    const float4* z4 = reinterpret_cast<const float4*>(z + ((size_t)i * NRES + j) * CZD);
    #pragma unroll 4
    for (int cc = 0; cc < 32; cc++) {
        float4 zz = z4[cc];
        #pragma unroll
        for (int h = 0; h < NHD; h++) {
            float4 wv = *reinterpret_cast<const float4*>(&wb_s[h * 128 + cc * 4]);
            acc[h] += zz.x * wv.x + zz.y * wv.y + zz.z * wv.z + zz.w * wv.w;
        }
    }
    const float* khj = g_khat + (size_t)j * 336;
    #pragma unroll
    for (int h = 0; h < NHD; h++) {
        float s = 0.f;
        #pragma unroll
        for (int d = 0; d < 7; d++) {
            float4 k4 = *reinterpret_cast<const float4*>(khj + h * 28 + d * 4);
            float4 q4 = *reinterpret_cast<const float4*>(&qh_s[h * 28 + d * 4]);
            s += k4.x * q4.x + k4.y * q4.y + k4.z * q4.z + k4.w * q4.w;
        }
        g_logits[((size_t)i * NHD + h) * NRES + j] = acc[h] + s;
    }
}

// ---------------- softmax (in place) + o_pair ----------------
__global__ void k_attn_out(const float* __restrict__ z) {
    extern __shared__ float sm[];
    float* a_t  = sm;                 // 768*12 floats (a transposed [j][h])
    float* part = sm + NRES * NHD;    // 2*12*128 floats
    int i = blockIdx.x;
    int t = threadIdx.x;
    int warp = t >> 5, lane = t & 31;
    for (int h = warp; h < NHD; h += 8) {
        float* row = g_logits + ((size_t)i * NHD + h) * NRES;
        float x[24];
        float mx = -1e30f;
        #pragma unroll
        for (int kk = 0; kk < 24; kk++) { x[kk] = row[lane + kk * 32]; mx = fmaxf(mx, x[kk]); }
        #pragma unroll
        for (int o = 16; o; o >>= 1) mx = fmaxf(mx, __shfl_xor_sync(0xffffffffu, mx, o));
        float s = 0.f;
        #pragma unroll
        for (int kk = 0; kk < 24; kk++) { x[kk] = __expf(x[kk] - mx); s += x[kk]; }
        #pragma unroll
        for (int o = 16; o; o >>= 1) s += __shfl_xor_sync(0xffffffffu, s, o);
        float r = 1.0f / s;
        #pragma unroll
        for (int kk = 0; kk < 24; kk++) {
            float a = x[kk] * r;
            int jj = lane + kk * 32;
            row[jj] = a;
            a_t[jj * NHD + h] = a;
        }
    }
    __syncthreads();
    int c = t & 127, half = t >> 7;
    const float* zp = z + ((size_t)i * NRES + half * 384) * CZD + c;
    float acc[NHD] = {};
    for (int j = 0; j < 384; j++) {
        float zv = zp[(size_t)j * CZD];
        const float* aa = a_t + (half * 384 + j) * NHD;
        float4 a0 = *reinterpret_cast<const float4*>(aa);
        float4 a1 = *reinterpret_cast<const float4*>(aa + 4);
        float4 a2 = *reinterpret_cast<const float4*>(aa + 8);
        acc[0] += a0.x * zv; acc[1]  += a0.y * zv; acc[2]  += a0.z * zv; acc[3]  += a0.w * zv;
        acc[4] += a1.x * zv; acc[5]  += a1.y * zv; acc[6]  += a1.z * zv; acc[7]  += a1.w * zv;
        acc[8] += a2.x * zv; acc[9]  += a2.y * zv; acc[10] += a2.z * zv; acc[11] += a2.w * zv;
    }
    #pragma unroll
    for (int h = 0; h < NHD; h++) part[(half * NHD + h) * 128 + c] = acc[h];
    __syncthreads();
    for (int idx = t; idx < NHD * 128; idx += 256)
        g_cat[(size_t)i * 2112 + 576 + idx] = part[idx] + part[NHD * 128 + idx];
}

// ---------------- o = a@v, o_pt_pre = a@v_pts (per head, tiled) ----------------
__global__ void k_ov() {
    __shared__ float a_s[64][65];
    __shared__ float v_s[64][40];
    int i0 = blockIdx.x * 64;
    int h  = blockIdx.y;
    int t  = threadIdx.x;
    int r = t & 63, cg = t >> 6;
    float acc[10] = {};
    for (int jt = 0; jt < NRES; jt += 64) {
        #pragma unroll
        for (int l = 0; l < 16; l++) {
            int idx = t + l * 256;
            a_s[idx >> 6][idx & 63] =
                g_logits[((size_t)(i0 + (idx >> 6)) * NHD + h) * NRES + jt + (idx & 63)];
        }
        #pragma unroll
        for (int l = 0; l < 10; l++) {
            int idx = t + l * 256;
            v_s[idx / 40][idx % 40] =
                g_vall[((size_t)(jt + idx / 40) * NHD + h) * 40 + idx % 40];
        }
        __syncthreads();
        #pragma unroll 8
        for (int k = 0; k < 64; k++) {
            float av = a_s[r][k];
            #pragma unroll
            for (int q = 0; q < 10; q++) acc[q] += av * v_s[k][cg * 10 + q];
        }
        __syncthreads();
    }
    #pragma unroll
    for (int q = 0; q < 10; q++) {
        int c = cg * 10 + q;
        if (c < 16) g_cat[(size_t)(i0 + r) * 2112 + h * 16 + c] = acc[q];
        else        g_optp[((size_t)(i0 + r) * NHD + h) * 24 + (c - 16)] = acc[q];
    }
}

// ---------------- inverse frame transform + norms into g_cat ----------------
__global__ void k_finalize(const float* __restrict__ r_rot, const float* __restrict__ r_trans) {
    int id = blockIdx.x * 256 + threadIdx.x;
    if (id >= NRES * 96) return;
    int n = id / 96, rr = id % 96;
    int h = rr >> 3, pv = rr & 7;
    const float* p = g_optp + ((size_t)n * NHD + h) * 24 + pv * 3;
    float d0 = p[0] - r_trans[n * 15 + 0];
    float d1 = p[1] - r_trans[n * 15 + 1];
    float d2 = p[2] - r_trans[n * 15 + 2];
    const float* R = r_rot + n * 45;
    float o0 = R[0] * d0 + R[3] * d1 + R[6] * d2;
    float o1 = R[1] * d0 + R[4] * d1 + R[7] * d2;
    float o2 = R[2] * d0 + R[5] * d1 + R[8] * d2;
    float nm = sqrtf(o0 * o0 + o1 * o1 + o2 * o2 + 1e-8f);
    float* cb = g_cat + (size_t)n * 2112 + 192;
    cb[rr] = o0; cb[96 + rr] = o1; cb[192 + rr] = o2; cb[288 + rr] = nm;
}

// ---------------- launch ----------------
extern "C" void kernel_launch(void* const* d_in, const int* in_sizes, int n_in,
                              void* d_out, int out_size) {
    const float* s       = (const float*)d_in[0];
    const float* z       = (const float*)d_in[1];
    const float* r_rot   = (const float*)d_in[2];
    const float* r_trans = (const float*)d_in[3];
    const float* mask    = (const float*)d_in[4];
    const float* wq      = (const float*)d_in[5];
    const float* bq      = (const float*)d_in[6];
    const float* wkv     = (const float*)d_in[7];
    const float* bkv     = (const float*)d_in[8];
    const float* wqp     = (const float*)d_in[9];
    const float* bqp     = (const float*)d_in[10];
    const float* wkvp    = (const float*)d_in[11];
    const float* bkvp    = (const float*)d_in[12];
    const float* wb      = (const float*)d_in[13];
    const float* bb      = (const float*)d_in[14];
    const float* head_w  = (const float*)d_in[15];
    const float* wout    = (const float*)d_in[16];
    const float* bout    = (const float*)d_in[17];
    const float* wexp    = (const float*)d_in[18];
    const float* bexp    = (const float*)d_in[19];
    const float* ln_g    = (const float*)d_in[20];
    const float* ln_b    = (const float*)d_in[21];
    // d_in[22]=ww, d_in[23]=bw : softmax over singleton axis -> weight == 1, unused.
    float* out = (float*)d_out;

    float *p_se = nullptr, *p_cat = nullptr, *p_part = nullptr;
    cudaGetSymbolAddress((void**)&p_se,   g_se);
    cudaGetSymbolAddress((void**)&p_cat,  g_cat);
    cudaGetSymbolAddress((void**)&p_part, g_part);

    // se0 = LN(s @ wexp[0:384]^T + bexp[0:384])
    k_gemm64<<<dim3(6, 12, 1), 256>>>(s, wexp, bexp, p_se, 384, 384, 24, 1, 0);
    k_ln<<<768, 128>>>(ln_g, ln_b);

    // fused projections into g_proj
    k_gemm_proj<<<dim3(18, 12), 256>>>(wq, bq, wkv, bkv, wqp, bqp, wkvp, bkvp);

    k_assemble<<<96, 256>>>(r_rot, r_trans, head_w);
    k_logits<<<dim3(3, 768), 256>>>(z, wb, bb, mask);
    k_attn_out<<<768, 256, (NRES * NHD + 2 * NHD * 128) * sizeof(float)>>>(z);
    k_ov<<<dim3(12, 12), 256>>>();
    k_finalize<<<288, 256>>>(r_rot, r_trans);

    // out = cat @ wout^T + bout  (split-K=2 partials, then combine)
    k_gemm64<<<dim3(6, 12, 2), 256>>>(p_cat, wout, nullptr, p_part, 2112, 384, 66, 0, NRES * CSD);
    k_combine<<<1152, 256>>>(bout, out);
}

// round 4
// speedup vs baseline: 1.5648x; 1.1207x over previous
#include <cuda_runtime.h>
#include <math.h>

#define NRES 768
#define CSD  384
#define CZD  128
#define NHD  12
#define INF_ 100000.0f

typedef unsigned long long u64;

// ---------------- packed f32x2 helpers ----------------
__device__ __forceinline__ void ffma2(u64& d, u64 a, u64 b) {
    asm("fma.rn.f32x2 %0, %1, %2, %0;" : "+l"(d) : "l"(a), "l"(b));
}
__device__ __forceinline__ u64 dup2(float x) {
    u64 r; asm("mov.b64 %0, {%1, %1};" : "=l"(r) : "f"(x)); return r;
}
__device__ __forceinline__ u64 pk2(float lo, float hi) {
    u64 r; asm("mov.b64 %0, {%1, %2};" : "=l"(r) : "f"(lo), "f"(hi)); return r;
}
__device__ __forceinline__ float2 up2(u64 v) {
    float lo, hi; asm("mov.b64 {%0, %1}, %2;" : "=f"(lo), "=f"(hi) : "l"(v));
    return make_float2(lo, hi);
}

// ---------------- scratch (device globals; no allocation) ----------------
__device__ float g_se[NRES * CSD];
__device__ float g_proj[NRES * 1152];         // [q(192) | kv(384) | qp(144) | kvp(432)]
__device__ float g_qhat[NRES * 336];          // per n: 12 heads x 28
__device__ float g_khat[NRES * 336];
__device__ float g_kc[NRES * NHD];
__device__ float g_vall[NRES * NHD * 40];     // per (n,h): v(16) + v_pts(24)
__device__ float g_optp[NRES * NHD * 24];
__device__ float g_cat[NRES * 2112];
__device__ float g_part[2][NRES * CSD];
__device__ float g_logits[NHD * NRES * NRES]; // [i][h][j]: qk-logits, then a

// =====================================================================
// fp32 GEMM with FFMA2: C = A(MxK) @ W(NxK)^T [+ bias]; 64x64 tile, BK=16.
// =====================================================================
__device__ __forceinline__ void mm16(const float* Ab, const float* Wb,
                                     int ty, int tx, u64 acc2[4][2]) {
    #pragma unroll
    for (int k = 0; k < 16; k++) {
        float4 av = *(const float4*)(Ab + k * 68 + ty * 4);
        ulonglong2 wv = *(const ulonglong2*)(Wb + k * 68 + tx * 4);
        u64 a0 = dup2(av.x), a1 = dup2(av.y), a2 = dup2(av.z), a3 = dup2(av.w);
        ffma2(acc2[0][0], a0, wv.x); ffma2(acc2[0][1], a0, wv.y);
        ffma2(acc2[1][0], a1, wv.x); ffma2(acc2[1][1], a1, wv.y);
        ffma2(acc2[2][0], a2, wv.x); ffma2(acc2[2][1], a2, wv.y);
        ffma2(acc2[3][0], a3, wv.x); ffma2(acc2[3][1], a3, wv.y);
    }
}

__global__ __launch_bounds__(256) void k_gemm64(
    const float* __restrict__ A, const float* __restrict__ W,
    const float* __restrict__ bias, float* __restrict__ C,
    int ld, int ldc, int nkt, int add_bias, int partStride)
{
    __shared__ __align__(16) float As[2][16][68];
    __shared__ __align__(16) float Ws[2][16][68];
    int t  = threadIdx.x;
    int m0 = blockIdx.y * 64, n0 = blockIdx.x * 64;
    int kt0 = blockIdx.z * nkt;
    C += (size_t)blockIdx.z * partStride;
    int lr = t >> 2, lk = (t & 3) * 4;
    const float* arow = A + (size_t)(m0 + lr) * ld + kt0 * 16 + lk;
    const float* wrow = W + (size_t)(n0 + lr) * ld + kt0 * 16 + lk;
    int tx = t & 15, ty = t >> 4;

    u64 acc2[4][2] = {};
    float4 ra = *(const float4*)arow;
    float4 rw = *(const float4*)wrow;
    int buf = 0;
    As[0][lk+0][lr]=ra.x; As[0][lk+1][lr]=ra.y; As[0][lk+2][lr]=ra.z; As[0][lk+3][lr]=ra.w;
    Ws[0][lk+0][lr]=rw.x; Ws[0][lk+1][lr]=rw.y; Ws[0][lk+2][lr]=rw.z; Ws[0][lk+3][lr]=rw.w;

    for (int kt = 0; kt < nkt - 1; kt++) {
        __syncthreads();
        ra = *(const float4*)(arow + (kt + 1) * 16);
        rw = *(const float4*)(wrow + (kt + 1) * 16);
        mm16(&As[buf][0][0], &Ws[buf][0][0], ty, tx, acc2);
        int nb = buf ^ 1;
        As[nb][lk+0][lr]=ra.x; As[nb][lk+1][lr]=ra.y; As[nb][lk+2][lr]=ra.z; As[nb][lk+3][lr]=ra.w;
        Ws[nb][lk+0][lr]=rw.x; Ws[nb][lk+1][lr]=rw.y; Ws[nb][lk+2][lr]=rw.z; Ws[nb][lk+3][lr]=rw.w;
        buf = nb;
    }
    __syncthreads();
    mm16(&As[buf][0][0], &Ws[buf][0][0], ty, tx, acc2);

    float4 bv = make_float4(0.f, 0.f, 0.f, 0.f);
    if (add_bias) bv = *(const float4*)(bias + n0 + tx * 4);
    #pragma unroll
    for (int a = 0; a < 4; a++) {
        float2 p0 = up2(acc2[a][0]), p1 = up2(acc2[a][1]);
        float4 r = make_float4(p0.x + bv.x, p0.y + bv.y, p1.x + bv.z, p1.y + bv.w);
        *(float4*)(C + (size_t)(m0 + ty * 4 + a) * ldc + n0 + tx * 4) = r;
    }
}

// Fused projection GEMM
__device__ __forceinline__ float proj_bias(int n, const float* bq, const float* bkv,
                                           const float* bqp, const float* bkvp) {
    if (n < 192) return bq[n];
    if (n < 576) return bkv[n - 192];
    if (n < 720) return bqp[n - 576];
    return bkvp[n - 720];
}

__global__ __launch_bounds__(256) void k_gemm_proj(
    const float* __restrict__ wq,  const float* __restrict__ bq,
    const float* __restrict__ wkv, const float* __restrict__ bkv,
    const float* __restrict__ wqp, const float* __restrict__ bqp,
    const float* __restrict__ wkvp,const float* __restrict__ bkvp)
{
    __shared__ __align__(16) float As[2][16][68];
    __shared__ __align__(16) float Ws[2][16][68];
    int t  = threadIdx.x;
    int m0 = blockIdx.y * 64, n0 = blockIdx.x * 64;
    int lr = t >> 2, lk = (t & 3) * 4;
    const float* arow = g_se + (size_t)(m0 + lr) * 384 + lk;
    int n = n0 + lr;
    const float* wbase; int nl;
    if      (n < 192) { wbase = wq;   nl = n; }
    else if (n < 576) { wbase = wkv;  nl = n - 192; }
    else if (n < 720) { wbase = wqp;  nl = n - 576; }
    else              { wbase = wkvp; nl = n - 720; }
    const float* wrow = wbase + (size_t)nl * 384 + lk;
    int tx = t & 15, ty = t >> 4;

    u64 acc2[4][2] = {};
    float4 ra = *(const float4*)arow;
    float4 rw = *(const float4*)wrow;
    int buf = 0;
    As[0][lk+0][lr]=ra.x; As[0][lk+1][lr]=ra.y; As[0][lk+2][lr]=ra.z; As[0][lk+3][lr]=ra.w;
    Ws[0][lk+0][lr]=rw.x; Ws[0][lk+1][lr]=rw.y; Ws[0][lk+2][lr]=rw.z; Ws[0][lk+3][lr]=rw.w;

    const int nkt = 24;
    for (int kt = 0; kt < nkt - 1; kt++) {
        __syncthreads();
        ra = *(const float4*)(arow + (kt + 1) * 16);
        rw = *(const float4*)(wrow + (kt + 1) * 16);
        mm16(&As[buf][0][0], &Ws[buf][0][0], ty, tx, acc2);
        int nb = buf ^ 1;
        As[nb][lk+0][lr]=ra.x; As[nb][lk+1][lr]=ra.y; As[nb][lk+2][lr]=ra.z; As[nb][lk+3][lr]=ra.w;
        Ws[nb][lk+0][lr]=rw.x; Ws[nb][lk+1][lr]=rw.y; Ws[nb][lk+2][lr]=rw.z; Ws[nb][lk+3][lr]=rw.w;
        buf = nb;
    }
    __syncthreads();
    mm16(&As[buf][0][0], &Ws[buf][0][0], ty, tx, acc2);

    int nc = n0 + tx * 4;
    float4 bv = make_float4(proj_bias(nc + 0, bq, bkv, bqp, bkvp),
                            proj_bias(nc + 1, bq, bkv, bqp, bkvp),
                            proj_bias(nc + 2, bq, bkv, bqp, bkvp),
                            proj_bias(nc + 3, bq, bkv, bqp, bkvp));
    #pragma unroll
    for (int a = 0; a < 4; a++) {
        float2 p0 = up2(acc2[a][0]), p1 = up2(acc2[a][1]);
        float4 r = make_float4(p0.x + bv.x, p0.y + bv.y, p1.x + bv.z, p1.y + bv.w);
        *(float4*)(g_proj + (size_t)(m0 + ty * 4 + a) * 1152 + nc) = r;
    }
}

__global__ void k_combine(const float* __restrict__ bout, float* __restrict__ out) {
    int i = blockIdx.x * 256 + threadIdx.x;
    out[i] = g_part[0][i] + g_part[1][i] + bout[i % 384];
}

// ---------------- LayerNorm ----------------
__global__ void k_ln(const float* __restrict__ gamma, const float* __restrict__ beta) {
    int n = blockIdx.x, t = threadIdx.x;
    float* row = g_se + (size_t)n * CSD;
    float x0 = row[t], x1 = row[t + 128], x2 = row[t + 256];
    float s1 = x0 + x1 + x2;
    float s2 = x0 * x0 + x1 * x1 + x2 * x2;
    __shared__ float r1[4], r2[4];
    #pragma unroll
    for (int o = 16; o; o >>= 1) {
        s1 += __shfl_xor_sync(0xffffffffu, s1, o);
        s2 += __shfl_xor_sync(0xffffffffu, s2, o);
    }
    if ((t & 31) == 0) { r1[t >> 5] = s1; r2[t >> 5] = s2; }
    __syncthreads();
    float ts1 = r1[0] + r1[1] + r1[2] + r1[3];
    float ts2 = r2[0] + r2[1] + r2[2] + r2[3];
    float mu  = ts1 * (1.f / 384.f);
    float var = ts2 * (1.f / 384.f) - mu * mu;
    float inv = rsqrtf(var + 1e-5f);
    row[t]       = (x0 - mu) * inv * gamma[t]       + beta[t];
    row[t + 128] = (x1 - mu) * inv * gamma[t + 128] + beta[t + 128];
    row[t + 256] = (x2 - mu) * inv * gamma[t + 256] + beta[t + 256];
}

// ---------------- assemble qhat/khat/kc/v/v_pts ----------------
__global__ void k_assemble(const float* __restrict__ r_rot, const float* __restrict__ r_trans,
                           const float* __restrict__ head_w) {
    int warp = threadIdx.x >> 5, lane = threadIdx.x & 31;
    if (lane >= 24) return;
    int n = blockIdx.x * 16 + warp * 2 + (lane / 12);
    int h = lane % 12;
    if (n >= NRES) return;
    float rot[9], t0[3];
    #pragma unroll
    for (int i = 0; i < 9; i++) rot[i] = r_rot[n * 45 + i];
    #pragma unroll
    for (int i = 0; i < 3; i++) t0[i] = r_trans[n * 15 + i];
    float hw = log1pf(expf(head_w[h])) * rsqrtf(54.0f);
    const float c1 = rsqrtf(48.0f);
    const float* P = g_proj + (size_t)n * 1152;
    float* qh = g_qhat + (size_t)n * 336 + h * 28;
    float* kh = g_khat + (size_t)n * 336 + h * 28;
    float* va = g_vall + ((size_t)n * NHD + h) * 40;
    #pragma unroll
    for (int c = 0; c < 16; c++) {
        qh[c] = c1 * P[h * 16 + c];
        kh[c] = P[192 + h * 32 + c];
        va[c] = P[192 + h * 32 + 16 + c];
    }
    #pragma unroll
    for (int pp = 0; pp < 4; pp++) {
        float l0 = P[576 +   0 + h * 4 + pp];
        float l1 = P[576 +  48 + h * 4 + pp];
        float l2 = P[576 +  96 + h * 4 + pp];
        #pragma unroll
        for (int i = 0; i < 3; i++) {
            float o = rot[i * 3] * l0 + rot[i * 3 + 1] * l1 + rot[i * 3 + 2] * l2 + t0[i];
            qh[16 + pp * 3 + i] = hw * o;
        }
    }
    float kc = 0.f;
    #pragma unroll
    for (int pp = 0; pp < 4; pp++) {
        float l0 = P[720 +   0 + h * 12 + pp];
        float l1 = P[720 + 144 + h * 12 + pp];
        float l2 = P[720 + 288 + h * 12 + pp];
        #pragma unroll
        for (int i = 0; i < 3; i++) {
            float o = rot[i * 3] * l0 + rot[i * 3 + 1] * l1 + rot[i * 3 + 2] * l2 + t0[i];
            kh[16 + pp * 3 + i] = o;
            kc += o * o;
        }
    }
    g_kc[n * NHD + h] = -0.5f * hw * kc;
    #pragma unroll
    for (int pv = 0; pv < 8; pv++) {
        int pp = 4 + pv;
        float l0 = P[720 +   0 + h * 12 + pp];
        float l1 = P[720 + 144 + h * 12 + pp];
        float l2 = P[720 + 288 + h * 12 + pp];
        #pragma unroll
        for (int i = 0; i < 3; i++) {
            float o = rot[i * 3] * l0 + rot[i * 3 + 1] * l1 + rot[i * 3 + 2] * l2 + t0[i];
            va[16 + pv * 3 + i] = o;
        }
    }
}

// ---------------- qk logits (K=28 GEMM) + kc + mask per head ----------------
__global__ __launch_bounds__(256) void k_qk(const float* __restrict__ mask) {
    __shared__ __align__(16) float Qs[28][68];
    __shared__ __align__(16) float Ks[28][68];
    __shared__ float kcs[64], uli[64], ulj[64];
    int h = blockIdx.z, i0 = blockIdx.y * 64, j0 = blockIdx.x * 64;
    int t = threadIdx.x;
    for (int idx = t; idx < 64 * 28; idx += 256) {
        int m = idx / 28, k = idx % 28;
        Qs[k][m] = g_qhat[(size_t)(i0 + m) * 336 + h * 28 + k];
        Ks[k][m] = g_khat[(size_t)(j0 + m) * 336 + h * 28 + k];
    }
    if (t < 64) {
        kcs[t] = g_kc[(j0 + t) * NHD + h];
        uli[t] = mask[(i0 + t) * 5];
        ulj[t] = mask[(j0 + t) * 5];
    }
    __syncthreads();
    int tx = t & 15, ty = t >> 4;
    u64 acc2[4][2] = {};
    #pragma unroll
    for (int k = 0; k < 28; k++) {
        float4 av = *(const float4*)(&Qs[k][ty * 4]);
        ulonglong2 wv = *(const ulonglong2*)(&Ks[k][tx * 4]);
        u64 a0 = dup2(av.x), a1 = dup2(av.y), a2 = dup2(av.z), a3 = dup2(av.w);
        ffma2(acc2[0][0], a0, wv.x); ffma2(acc2[0][1], a0, wv.y);
        ffma2(acc2[1][0], a1, wv.x); ffma2(acc2[1][1], a1, wv.y);
        ffma2(acc2[2][0], a2, wv.x); ffma2(acc2[2][1], a2, wv.y);
        ffma2(acc2[3][0], a3, wv.x); ffma2(acc2[3][1], a3, wv.y);
    }
    int jb = tx * 4;
    #pragma unroll
    for (int a = 0; a < 4; a++) {
        int i = i0 + ty * 4 + a;
        float mi = uli[ty * 4 + a];
        float2 p0 = up2(acc2[a][0]), p1 = up2(acc2[a][1]);
        float4 r;
        r.x = p0.x + kcs[jb + 0] + INF_ * (mi * ulj[jb + 0] - 1.f);
        r.y = p0.y + kcs[jb + 1] + INF_ * (mi * ulj[jb + 1] - 1.f);
        r.z = p1.x + kcs[jb + 2] + INF_ * (mi * ulj[jb + 2] - 1.f);
        r.w = p1.y + kcs[jb + 3] + INF_ * (mi * ulj[jb + 3] - 1.f);
        *(float4*)(&g_logits[((size_t)i * NHD + h) * NRES + j0 + jb]) = r;
    }
}

// ---------------- fused: z@wb + qk-logits -> softmax -> a, o_pair ----------------
// grid = 768 (one i per block), 256 threads, ~87KB dynamic smem
#define ATTN_SMEM (33792 + 36864 + 6144 + 12288)
__global__ __launch_bounds__(256) void k_attn(const float* __restrict__ z,
                                              const float* __restrict__ wb) {
    extern __shared__ __align__(16) unsigned char smraw[];
    float4* zs4 = (float4*)smraw;                                  // 64 x 33 float4
    float*  a_s = (float*)(smraw + 33792);                         // 768 x 12
    u64*    wb2 = (u64*)(smraw + 33792 + 36864);                   // 128 x 6
    float*  red = (float*)(smraw + 33792 + 36864 + 6144);          // 3072 (reused ph.B)

    int i = blockIdx.x;
    int t = threadIdx.x;
    const float c2 = 0.57735026918962576f; // sqrt(1/3)

    // stage wb pairs scaled by c2: wb2[c*6+p] = (c2*wb[2p][c], c2*wb[2p+1][c])
    for (int e = t; e < 768; e += 256) {
        int c = e / 6, p = e % 6;
        wb2[e] = pk2(c2 * wb[(2 * p) * 128 + c], c2 * wb[(2 * p + 1) * 128 + c]);
    }
    __syncthreads();

    // ---- phase A: logits = qk + z@wb, per 64-j tile ----
    for (int jt = 0; jt < 12; jt++) {
        int j0 = jt * 64;
        const float4* zrow = (const float4*)(z + ((size_t)i * NRES + j0) * CZD);
        #pragma unroll
        for (int l = 0; l < 8; l++) {
            int idx = t + l * 256;
            int jr = idx >> 5, c4 = idx & 31;
            zs4[jr * 33 + c4] = zrow[jr * 32 + c4];
        }
        __syncthreads();
        int j = t & 63, q = t >> 6;
        u64 acc2[6] = {};
        const float4* zj = zs4 + j * 33 + q * 8;
        #pragma unroll
        for (int c4 = 0; c4 < 8; c4++) {
            float4 zz = zj[c4];
            int cb = (q * 32 + c4 * 4) * 6;
            u64 z0 = dup2(zz.x), z1 = dup2(zz.y), z2 = dup2(zz.z), z3 = dup2(zz.w);
            #pragma unroll
            for (int p = 0; p < 6; p++) ffma2(acc2[p], z0, wb2[cb + p]);
            #pragma unroll
            for (int p = 0; p < 6; p++) ffma2(acc2[p], z1, wb2[cb + 6 + p]);
            #pragma unroll
            for (int p = 0; p < 6; p++) ffma2(acc2[p], z2, wb2[cb + 12 + p]);
            #pragma unroll
            for (int p = 0; p < 6; p++) ffma2(acc2[p], z3, wb2[cb + 18 + p]);
        }
        #pragma unroll
        for (int p = 0; p < 6; p++) {
            float2 v = up2(acc2[p]);
            red[(q * 64 + j) * 12 + 2 * p]     = v.x;
            red[(q * 64 + j) * 12 + 2 * p + 1] = v.y;
        }
        __syncthreads();
        for (int e = t; e < 768; e += 256) {
            int hh = e >> 6, jj = e & 63;
            float s = red[jj * 12 + hh] + red[(64 + jj) * 12 + hh]
                    + red[(128 + jj) * 12 + hh] + red[(192 + jj) * 12 + hh];
            s += g_logits[((size_t)i * NHD + hh) * NRES + j0 + jj];
            a_s[(j0 + jj) * 12 + hh] = s;
        }
        __syncthreads();
    }

    // ---- softmax per head over j, write a to smem + global ----
    {
        int warp = t >> 5, lane = t & 31;
        for (int h = warp; h < NHD; h += 8) {
            float x[24];
            float mx = -1e30f;
            #pragma unroll
            for (int kk = 0; kk < 24; kk++) {
                x[kk] = a_s[(lane + kk * 32) * 12 + h];
                mx = fmaxf(mx, x[kk]);
            }
            #pragma unroll
            for (int o = 16; o; o >>= 1) mx = fmaxf(mx, __shfl_xor_sync(0xffffffffu, mx, o));
            float s = 0.f;
            #pragma unroll
            for (int kk = 0; kk < 24; kk++) { x[kk] = __expf(x[kk] - mx); s += x[kk]; }
            #pragma unroll
            for (int o = 16; o; o >>= 1) s += __shfl_xor_sync(0xffffffffu, s, o);
            float r = 1.0f / s;
            #pragma unroll
            for (int kk = 0; kk < 24; kk++) {
                float a = x[kk] * r;
                int jj = lane + kk * 32;
                a_s[jj * 12 + h] = a;
                g_logits[((size_t)i * NHD + h) * NRES + jj] = a;
            }
        }
    }
    __syncthreads();

    // ---- phase B: o_pair[h][c] = sum_j a[j][h] * z[i][j][c] (z from L2) ----
    {
        int c = t & 127, half = t >> 7;
        const float* zp = z + ((size_t)i * NRES + half * 384) * CZD + c;
        u64 acc2[6] = {};
        #pragma unroll 4
        for (int j2 = 0; j2 < 384; j2++) {
            float zv = zp[(size_t)j2 * CZD];
            u64 zd = dup2(zv);
            const u64* aj = (const u64*)(a_s + (half * 384 + j2) * 12);
            #pragma unroll
            for (int p = 0; p < 6; p++) ffma2(acc2[p], zd, aj[p]);
        }
        float* part = red;  // reuse
        #pragma unroll
        for (int p = 0; p < 6; p++) {
            float2 v = up2(acc2[p]);
            part[(half * 12 + 2 * p) * 128 + c]     = v.x;
            part[(half * 12 + 2 * p + 1) * 128 + c] = v.y;
        }
        __syncthreads();
        for (int e = t; e < NHD * 128; e += 256)
            g_cat[(size_t)i * 2112 + 576 + e] = part[e] + part[1536 + e];
    }
}

// ---------------- o = a@v, o_pt_pre = a@v_pts ----------------
__global__ void k_ov() {
    __shared__ float a_s[64][65];
    __shared__ float v_s[64][40];
    int i0 = blockIdx.x * 64;
    int h  = blockIdx.y;
    int t  = threadIdx.x;
    int r = t & 63, cg = t >> 6;
    u64 acc2[5] = {};
    for (int jt = 0; jt < NRES; jt += 64) {
        #pragma unroll
        for (int l = 0; l < 16; l++) {
            int idx = t + l * 256;
            a_s[idx >> 6][idx & 63] =
                g_logits[((size_t)(i0 + (idx >> 6)) * NHD + h) * NRES + jt + (idx & 63)];
        }
        #pragma unroll
        for (int l = 0; l < 10; l++) {
            int idx = t + l * 256;
            v_s[idx / 40][idx % 40] =
                g_vall[((size_t)(jt + idx / 40) * NHD + h) * 40 + idx % 40];
        }
        __syncthreads();
        #pragma unroll 8
        for (int k = 0; k < 64; k++) {
            u64 ad = dup2(a_s[r][k]);
            const u64* vrow = (const u64*)(&v_s[k][cg * 10]);
            #pragma unroll
            for (int p = 0; p < 5; p++) ffma2(acc2[p], ad, vrow[p]);
        }
        __syncthreads();
    }
    #pragma unroll
    for (int p = 0; p < 5; p++) {
        float2 v = up2(acc2[p]);
        int c0 = cg * 10 + 2 * p;
        float vals[2] = {v.x, v.y};
        #pragma unroll
        for (int w = 0; w < 2; w++) {
            int c = c0 + w;
            if (c < 16) g_cat[(size_t)(i0 + r) * 2112 + h * 16 + c] = vals[w];
            else        g_optp[((size_t)(i0 + r) * NHD + h) * 24 + (c - 16)] = vals[w];
        }
    }
}

// ---------------- inverse frame transform + norms ----------------
__global__ void k_finalize(const float* __restrict__ r_rot, const float* __restrict__ r_trans) {
    int id = blockIdx.x * 256 + threadIdx.x;
    if (id >= NRES * 96) return;
    int n = id / 96, rr = id % 96;
    int h = rr >> 3, pv = rr & 7;
    const float* p = g_optp + ((size_t)n * NHD + h) * 24 + pv * 3;
    float d0 = p[0] - r_trans[n * 15 + 0];
    float d1 = p[1] - r_trans[n * 15 + 1];
    float d2 = p[2] - r_trans[n * 15 + 2];
    const float* R = r_rot + n * 45;
    float o0 = R[0] * d0 + R[3] * d1 + R[6] * d2;
    float o1 = R[1] * d0 + R[4] * d1 + R[7] * d2;
    float o2 = R[2] * d0 + R[5] * d1 + R[8] * d2;
    float nm = sqrtf(o0 * o0 + o1 * o1 + o2 * o2 + 1e-8f);
    float* cb = g_cat + (size_t)n * 2112 + 192;
    cb[rr] = o0; cb[96 + rr] = o1; cb[192 + rr] = o2; cb[288 + rr] = nm;
}

// ---------------- launch ----------------
extern "C" void kernel_launch(void* const* d_in, const int* in_sizes, int n_in,
                              void* d_out, int out_size) {
    const float* s       = (const float*)d_in[0];
    const float* z       = (const float*)d_in[1];
    const float* r_rot   = (const float*)d_in[2];
    const float* r_trans = (const float*)d_in[3];
    const float* mask    = (const float*)d_in[4];
    const float* wq      = (const float*)d_in[5];
    const float* bq      = (const float*)d_in[6];
    const float* wkv     = (const float*)d_in[7];
    const float* bkv     = (const float*)d_in[8];
    const float* wqp     = (const float*)d_in[9];
    const float* bqp     = (const float*)d_in[10];
    const float* wkvp    = (const float*)d_in[11];
    const float* bkvp    = (const float*)d_in[12];
    const float* wb      = (const float*)d_in[13];
    const float* head_w  = (const float*)d_in[15];
    const float* wout    = (const float*)d_in[16];
    const float* bout    = (const float*)d_in[17];
    const float* wexp    = (const float*)d_in[18];
    const float* bexp    = (const float*)d_in[19];
    const float* ln_g    = (const float*)d_in[20];
    const float* ln_b    = (const float*)d_in[21];
    // d_in[14]=bb dropped (softmax-invariant); d_in[22]/[23]=ww/bw (weight==1).
    float* out = (float*)d_out;

    float *p_se = nullptr, *p_cat = nullptr, *p_part = nullptr;
    cudaGetSymbolAddress((void**)&p_se,   g_se);
    cudaGetSymbolAddress((void**)&p_cat,  g_cat);
    cudaGetSymbolAddress((void**)&p_part, g_part);

    static int attn_cfg = 0;
    if (!attn_cfg) {
        cudaFuncSetAttribute(k_attn, cudaFuncAttributeMaxDynamicSharedMemorySize, ATTN_SMEM);
        attn_cfg = 1;
    }

    k_gemm64<<<dim3(6, 12, 1), 256>>>(s, wexp, bexp, p_se, 384, 384, 24, 1, 0);
    k_ln<<<768, 128>>>(ln_g, ln_b);
    k_gemm_proj<<<dim3(18, 12), 256>>>(wq, bq, wkv, bkv, wqp, bqp, wkvp, bkvp);
    k_assemble<<<48, 256>>>(r_rot, r_trans, head_w);
    k_qk<<<dim3(12, 12, 12), 256>>>(mask);
    k_attn<<<768, 256, ATTN_SMEM>>>(z, wb);
    k_ov<<<dim3(12, 12), 256>>>();
    k_finalize<<<288, 256>>>(r_rot, r_trans);
    k_gemm64<<<dim3(6, 12, 2), 256>>>(p_cat, wout, nullptr, p_part, 2112, 384, 66, 0, NRES * CSD);
    k_combine<<<1152, 256>>>(bout, out);
}